// round 3
// baseline (speedup 1.0000x reference)
#include <cuda_runtime.h>

#define NN 50000
#define IC 512
#define OC 128
#define NE 1600000

typedef unsigned long long ull;

// ---------------------------------------------------------------------------
// Scratch (static __device__ — no allocation in kernel_launch)
__device__ int   g_deg[NN];
__device__ float g_dis[NN];
__device__ float g_y[(size_t)NN * OC];    // (x @ W_enc) * dis[row]
__device__ float g_agg[(size_t)NN * OC];  // sum of y[src] per dst
// k-pair-interleaved weights: element (kp, n) = (W[2kp][n], W[2kp+1][n])
// stored as ulonglong2 covering cols (2u, 2u+1)
__device__ ulonglong2 g_WpE[256 * 64];    // enc: 256 kp x 128 cols -> 64 ull2/kp
__device__ ulonglong2 g_WpD[64 * 256];    // dec:  64 kp x 512 cols -> 256 ull2/kp

// packed f32x2 FMA: d = a*b + d elementwise on (lo,hi)
__device__ __forceinline__ void fma2(ull& d, ull a, ull b) {
    asm("fma.rn.f32x2 %0, %1, %2, %0;" : "+l"(d) : "l"(a), "l"(b));
}
__device__ __forceinline__ float2 up2(ull a) {
    float2 r;
    asm("mov.b64 {%0, %1}, %2;" : "=f"(r.x), "=f"(r.y) : "l"(a));
    return r;
}

// ---------------------------------------------------------------------------
// K0: zero deg + agg
__global__ void k_zero() {
    int i = blockIdx.x * blockDim.x + threadIdx.x;
    if (i < NN) g_deg[i] = 0;
    const int tot4 = NN * OC / 4;
    float4* a4 = (float4*)g_agg;
    for (int j = i; j < tot4; j += gridDim.x * blockDim.x)
        a4[j] = make_float4(0.f, 0.f, 0.f, 0.f);
}

// K1: dst-degree histogram
__global__ void k_deg(const int* __restrict__ ei) {
    int i = blockIdx.x * blockDim.x + threadIdx.x;
    if (i < NE) atomicAdd(&g_deg[ei[NE + i]], 1);
}

// K2: dis = rsqrt(deg + 1)
__global__ void k_dis() {
    int i = blockIdx.x * blockDim.x + threadIdx.x;
    if (i < NN) g_dis[i] = rsqrtf((float)(g_deg[i] + 1));
}

// K_prep: build k-pair interleaved weight layouts (both are 16384 float4)
__global__ void k_prep(const float* __restrict__ We, const float* __restrict__ Wd) {
    int i = blockIdx.x * blockDim.x + threadIdx.x;
    if (i < 256 * 64) {  // enc: kp in [0,256), n2 = col pair in [0,64)
        int kp = i >> 6, n2 = i & 63;
        float4 v;
        v.x = We[(2 * kp) * OC + 2 * n2];
        v.y = We[(2 * kp + 1) * OC + 2 * n2];
        v.z = We[(2 * kp) * OC + 2 * n2 + 1];
        v.w = We[(2 * kp + 1) * OC + 2 * n2 + 1];
        ((float4*)g_WpE)[i] = v;
    }
    if (i < 64 * 256) {  // dec: kp in [0,64), n2 in [0,256)
        int kp = i >> 8, n2 = i & 255;
        float4 v;
        v.x = Wd[(2 * kp) * IC + 2 * n2];
        v.y = Wd[(2 * kp + 1) * IC + 2 * n2];
        v.z = Wd[(2 * kp) * IC + 2 * n2 + 1];
        v.w = Wd[(2 * kp + 1) * IC + 2 * n2 + 1];
        ((float4*)g_WpD)[i] = v;
    }
}

// ---------------------------------------------------------------------------
// K3: y = (x @ W_enc) * dis[row] via packed f32x2 FMA, K-paired.
// 32 rows/block, 128 threads. warp w: rows w*8 + rg*4 .. +3 (rg = lane>>4).
// cols: cg = lane&15 -> cols cg*8 .. cg*8+7.
__global__ __launch_bounds__(128) void k_gemm1(const float* __restrict__ x) {
    const int tid = threadIdx.x;
    const int warp = tid >> 5, lane = tid & 31;
    const int cg = lane & 15, rg = lane >> 4;
    const int row0 = blockIdx.x * 32 + warp * 8 + rg * 4;

    const ulonglong2* __restrict__ xq = (const ulonglong2*)x;  // 128 per row

    int r[4];
#pragma unroll
    for (int m = 0; m < 4; m++) r[m] = min(row0 + m, NN - 1);

    ull acc[4][8];
#pragma unroll
    for (int m = 0; m < 4; m++)
#pragma unroll
        for (int j = 0; j < 8; j++) acc[m][j] = 0ull;

    for (int kp = 0; kp < 256; kp += 4) {  // k step 8
        ulonglong2 xv[4][2];
#pragma unroll
        for (int m = 0; m < 4; m++) {
            size_t base = (size_t)r[m] * 128 + (kp >> 1);
            xv[m][0] = xq[base];
            xv[m][1] = xq[base + 1];
        }
#pragma unroll
        for (int kp2 = 0; kp2 < 4; kp2++) {
            const ulonglong2* wrow = &g_WpE[(kp + kp2) * 64 + cg * 4];
            ulonglong2 w0 = wrow[0], w1 = wrow[1], w2 = wrow[2], w3 = wrow[3];
#pragma unroll
            for (int m = 0; m < 4; m++) {
                ull xm = (kp2 & 1) ? xv[m][kp2 >> 1].y : xv[m][kp2 >> 1].x;
                fma2(acc[m][0], xm, w0.x);
                fma2(acc[m][1], xm, w0.y);
                fma2(acc[m][2], xm, w1.x);
                fma2(acc[m][3], xm, w1.y);
                fma2(acc[m][4], xm, w2.x);
                fma2(acc[m][5], xm, w2.y);
                fma2(acc[m][6], xm, w3.x);
                fma2(acc[m][7], xm, w3.y);
            }
        }
    }

#pragma unroll
    for (int m = 0; m < 4; m++) {
        int row = row0 + m;
        if (row >= NN) continue;
        float d = g_dis[row];
        float v[8];
#pragma unroll
        for (int j = 0; j < 8; j++) {
            float2 p = up2(acc[m][j]);
            v[j] = (p.x + p.y) * d;
        }
        float4* o = (float4*)(g_y + (size_t)row * OC + cg * 8);
        o[0] = make_float4(v[0], v[1], v[2], v[3]);
        o[1] = make_float4(v[4], v[5], v[6], v[7]);
    }
}

// ---------------------------------------------------------------------------
// K4: edge scatter-add: agg[dst] += y[src].  One warp per edge, float4 lanes,
// vector reduction atomics.
__global__ __launch_bounds__(256) void k_edges(const int* __restrict__ ei) {
    long long gt = (long long)blockIdx.x * blockDim.x + threadIdx.x;
    int e = (int)(gt >> 5);
    if (e >= NE) return;
    int lane = threadIdx.x & 31;
    int s = ei[e];
    int d = ei[NE + e];
    float4 v = ((const float4*)g_y)[(size_t)s * 32 + lane];
    float* a = g_agg + (size_t)d * OC + lane * 4;
    asm volatile("red.global.add.v4.f32 [%0], {%1,%2,%3,%4};"
                 :: "l"(a), "f"(v.x), "f"(v.y), "f"(v.z), "f"(v.w)
                 : "memory");
}

// ---------------------------------------------------------------------------
// K5: fused epilogue + decode GEMM (f32x2, K-paired) + softmax.
// 8 nodes/block, 128 threads. cg = tid&63 -> cols cg*8..+7; rg = tid>>6 ->
// local nodes rg*4..rg*4+3.
__global__ __launch_bounds__(128) void k_dec(const float* __restrict__ b,
                                             float* __restrict__ out) {
    __shared__ __align__(16) float hs[8 * OC];  // 4 KB
    __shared__ float red[4][4];                 // [warp][local m]
    const int tid = threadIdx.x;
    const int warp = tid >> 5, lane = tid & 31;
    const int n0 = blockIdx.x * 8;
    const int cg = tid & 63, rg = tid >> 6;

    // h = relu(dis*(agg + y) + bias)
#pragma unroll
    for (int i = tid; i < 8 * OC; i += 128) {
        int m = i >> 7, c = i & 127;
        int n = n0 + m;
        size_t off = (size_t)n * OC + c;
        float v = g_dis[n] * (g_agg[off] + g_y[off]) + b[c];
        hs[i] = fmaxf(v, 0.f);
    }
    __syncthreads();

    const ulonglong2* hq = (const ulonglong2*)hs;  // 32 per node

    ull acc[4][8];
#pragma unroll
    for (int m = 0; m < 4; m++)
#pragma unroll
        for (int j = 0; j < 8; j++) acc[m][j] = 0ull;

    for (int kp = 0; kp < 64; kp += 4) {  // k step 8 over OC=128
        ulonglong2 hv[4][2];
#pragma unroll
        for (int m = 0; m < 4; m++) {
            int base = (rg * 4 + m) * 32 + (kp >> 1);
            hv[m][0] = hq[base];
            hv[m][1] = hq[base + 1];
        }
#pragma unroll
        for (int kp2 = 0; kp2 < 4; kp2++) {
            const ulonglong2* wrow = &g_WpD[(kp + kp2) * 256 + cg * 4];
            ulonglong2 w0 = wrow[0], w1 = wrow[1], w2 = wrow[2], w3 = wrow[3];
#pragma unroll
            for (int m = 0; m < 4; m++) {
                ull xm = (kp2 & 1) ? hv[m][kp2 >> 1].y : hv[m][kp2 >> 1].x;
                fma2(acc[m][0], xm, w0.x);
                fma2(acc[m][1], xm, w0.y);
                fma2(acc[m][2], xm, w1.x);
                fma2(acc[m][3], xm, w1.y);
                fma2(acc[m][4], xm, w2.x);
                fma2(acc[m][5], xm, w2.y);
                fma2(acc[m][6], xm, w3.x);
                fma2(acc[m][7], xm, w3.y);
            }
        }
    }

    // logits for node (rg*4+m), cols cg*8+j
    float v[4][8];
#pragma unroll
    for (int m = 0; m < 4; m++) {
#pragma unroll
        for (int j = 0; j < 8; j++) {
            float2 p = up2(acc[m][j]);
            v[m][j] = p.x + p.y;
        }
    }

    // softmax over 512 cols = 64 cgs = 2 warps (warps rg*2, rg*2+1)
    // 1) max
#pragma unroll
    for (int m = 0; m < 4; m++) {
        float lm = v[m][0];
#pragma unroll
        for (int j = 1; j < 8; j++) lm = fmaxf(lm, v[m][j]);
#pragma unroll
        for (int o = 16; o; o >>= 1)
            lm = fmaxf(lm, __shfl_xor_sync(0xffffffffu, lm, o));
        if (lane == 0) red[warp][m] = lm;
    }
    __syncthreads();
    float rm[4];
#pragma unroll
    for (int m = 0; m < 4; m++)
        rm[m] = fmaxf(red[rg * 2][m], red[rg * 2 + 1][m]);
    __syncthreads();

    // 2) exp + sum
#pragma unroll
    for (int m = 0; m < 4; m++) {
        float ls = 0.f;
#pragma unroll
        for (int j = 0; j < 8; j++) {
            v[m][j] = __expf(v[m][j] - rm[m]);
            ls += v[m][j];
        }
#pragma unroll
        for (int o = 16; o; o >>= 1)
            ls += __shfl_xor_sync(0xffffffffu, ls, o);
        if (lane == 0) red[warp][m] = ls;
    }
    __syncthreads();

#pragma unroll
    for (int m = 0; m < 4; m++) {
        float inv = 1.f / (red[rg * 2][m] + red[rg * 2 + 1][m]);
        int row = n0 + rg * 4 + m;
        float4* o = (float4*)(out + (size_t)row * IC + cg * 8);
        o[0] = make_float4(v[m][0] * inv, v[m][1] * inv, v[m][2] * inv, v[m][3] * inv);
        o[1] = make_float4(v[m][4] * inv, v[m][5] * inv, v[m][6] * inv, v[m][7] * inv);
    }
}

// ---------------------------------------------------------------------------
extern "C" void kernel_launch(void* const* d_in, const int* in_sizes, int n_in,
                              void* d_out, int out_size) {
    const float* x    = (const float*)d_in[0];
    const int*   ei   = (const int*)d_in[1];
    const float* Wenc = (const float*)d_in[2];
    const float* benc = (const float*)d_in[3];
    const float* Wdec = (const float*)d_in[4];
    float*       out  = (float*)d_out;

    k_zero<<<2048, 256>>>();
    k_prep<<<64, 256>>>(Wenc, Wdec);
    k_deg<<<(NE + 255) / 256, 256>>>(ei);
    k_dis<<<(NN + 255) / 256, 256>>>();
    k_gemm1<<<(NN + 31) / 32, 128>>>(x);
    {
        long long threads = (long long)NE * 32;
        int blocks = (int)((threads + 255) / 256);
        k_edges<<<blocks, 256>>>(ei);
    }
    k_dec<<<NN / 8, 128>>>(benc, out);
}

// round 4
// speedup vs baseline: 1.7586x; 1.7586x over previous
#include <cuda_runtime.h>

#define NN 50000
#define IC 512
#define OC 128
#define NE 1600000

typedef unsigned long long ull;

// ---------------------------------------------------------------------------
// Scratch (static __device__ — no allocation in kernel_launch)
__device__ int   g_deg[NN];
__device__ float g_dis[NN];
__device__ float g_y[(size_t)NN * OC];    // (x @ W_enc) * dis[row]
__device__ float g_agg[(size_t)NN * OC];  // sum of y[src] per dst

// k-pair weights, lane-contiguous layout: [kp][j][cg] of ull2.
// Entry = cols (cg*8 + 2j, cg*8 + 2j + 1), each col as pair (W[2kp][c], W[2kp+1][c]).
// enc: 256 kp x 4 j x 16 cg ; dec: 64 kp x 4 j x 64 cg
__device__ ulonglong2 g_WpE[256 * 4 * 16];
__device__ ulonglong2 g_WpD[64 * 4 * 64];

// packed f32x2 FMA: d = a*b + d elementwise on (lo,hi)
__device__ __forceinline__ void fma2(ull& d, ull a, ull b) {
    asm("fma.rn.f32x2 %0, %1, %2, %0;" : "+l"(d) : "l"(a), "l"(b));
}
__device__ __forceinline__ float2 up2(ull a) {
    float2 r;
    asm("mov.b64 {%0, %1}, %2;" : "=f"(r.x), "=f"(r.y) : "l"(a));
    return r;
}

// ---------------------------------------------------------------------------
// K0: zero deg + agg
__global__ void k_zero() {
    int i = blockIdx.x * blockDim.x + threadIdx.x;
    if (i < NN) g_deg[i] = 0;
    const int tot4 = NN * OC / 4;
    float4* a4 = (float4*)g_agg;
    for (int j = i; j < tot4; j += gridDim.x * blockDim.x)
        a4[j] = make_float4(0.f, 0.f, 0.f, 0.f);
}

// K1: dst-degree histogram
__global__ void k_deg(const int* __restrict__ ei) {
    int i = blockIdx.x * blockDim.x + threadIdx.x;
    if (i < NE) atomicAdd(&g_deg[ei[NE + i]], 1);
}

// K2: dis = rsqrt(deg + 1)
__global__ void k_dis() {
    int i = blockIdx.x * blockDim.x + threadIdx.x;
    if (i < NN) g_dis[i] = rsqrtf((float)(g_deg[i] + 1));
}

// K_prep: build lane-contiguous k-pair weight layouts
__global__ void k_prep(const float* __restrict__ We, const float* __restrict__ Wd) {
    int i = blockIdx.x * blockDim.x + threadIdx.x;
    if (i < 256 * 4 * 16) {  // enc
        int kp = i >> 6, j = (i >> 4) & 3, cg = i & 15;
        int c = cg * 8 + 2 * j;
        float4 v;
        v.x = We[(2 * kp) * OC + c];
        v.y = We[(2 * kp + 1) * OC + c];
        v.z = We[(2 * kp) * OC + c + 1];
        v.w = We[(2 * kp + 1) * OC + c + 1];
        ((float4*)g_WpE)[i] = v;
    }
    if (i < 64 * 4 * 64) {  // dec
        int kp = i >> 8, j = (i >> 6) & 3, cg = i & 63;
        int c = cg * 8 + 2 * j;
        float4 v;
        v.x = Wd[(2 * kp) * IC + c];
        v.y = Wd[(2 * kp + 1) * IC + c];
        v.z = Wd[(2 * kp) * IC + c + 1];
        v.w = Wd[(2 * kp + 1) * IC + c + 1];
        ((float4*)g_WpD)[i] = v;
    }
}

// ---------------------------------------------------------------------------
// K3: y = (x @ W_enc) * dis[row] via packed f32x2 FMA, K-paired.
// 32 rows/block, 128 threads. warp w: rows w*8 + rg*4 .. +3 (rg = lane>>4).
// cols: cg = lane&15 -> cols cg*8 .. cg*8+7.
__global__ __launch_bounds__(128) void k_gemm1(const float* __restrict__ x) {
    const int tid = threadIdx.x;
    const int warp = tid >> 5, lane = tid & 31;
    const int cg = lane & 15, rg = lane >> 4;
    const int row0 = blockIdx.x * 32 + warp * 8 + rg * 4;

    const ulonglong2* __restrict__ xq = (const ulonglong2*)x;  // 128 per row

    int r[4];
#pragma unroll
    for (int m = 0; m < 4; m++) r[m] = min(row0 + m, NN - 1);

    ull acc[4][8];
#pragma unroll
    for (int m = 0; m < 4; m++)
#pragma unroll
        for (int j = 0; j < 8; j++) acc[m][j] = 0ull;

    for (int kp = 0; kp < 256; kp += 4) {  // k step 8
        ulonglong2 xv[4][2];
#pragma unroll
        for (int m = 0; m < 4; m++) {
            size_t base = (size_t)r[m] * 128 + (kp >> 1);
            xv[m][0] = xq[base];
            xv[m][1] = xq[base + 1];
        }
#pragma unroll
        for (int kp2 = 0; kp2 < 4; kp2++) {
            const ulonglong2* wbase = &g_WpE[(kp + kp2) * 64 + cg];  // [j*16 + cg]
            ulonglong2 w0 = wbase[0];
            ulonglong2 w1 = wbase[16];
            ulonglong2 w2 = wbase[32];
            ulonglong2 w3 = wbase[48];
#pragma unroll
            for (int m = 0; m < 4; m++) {
                ull xm = (kp2 & 1) ? xv[m][kp2 >> 1].y : xv[m][kp2 >> 1].x;
                fma2(acc[m][0], xm, w0.x);
                fma2(acc[m][1], xm, w0.y);
                fma2(acc[m][2], xm, w1.x);
                fma2(acc[m][3], xm, w1.y);
                fma2(acc[m][4], xm, w2.x);
                fma2(acc[m][5], xm, w2.y);
                fma2(acc[m][6], xm, w3.x);
                fma2(acc[m][7], xm, w3.y);
            }
        }
    }

#pragma unroll
    for (int m = 0; m < 4; m++) {
        int row = row0 + m;
        if (row >= NN) continue;
        float d = g_dis[row];
        float v[8];
#pragma unroll
        for (int j = 0; j < 8; j++) {
            float2 p = up2(acc[m][j]);
            v[j] = (p.x + p.y) * d;
        }
        float4* o = (float4*)(g_y + (size_t)row * OC + cg * 8);
        o[0] = make_float4(v[0], v[1], v[2], v[3]);
        o[1] = make_float4(v[4], v[5], v[6], v[7]);
    }
}

// ---------------------------------------------------------------------------
// K4: edge scatter-add: agg[dst] += y[src].  One warp per edge, float4 lanes,
// vector reduction atomics.
__global__ __launch_bounds__(256) void k_edges(const int* __restrict__ ei) {
    long long gt = (long long)blockIdx.x * blockDim.x + threadIdx.x;
    int e = (int)(gt >> 5);
    if (e >= NE) return;
    int lane = threadIdx.x & 31;
    int s = ei[e];
    int d = ei[NE + e];
    float4 v = ((const float4*)g_y)[(size_t)s * 32 + lane];
    float* a = g_agg + (size_t)d * OC + lane * 4;
    asm volatile("red.global.add.v4.f32 [%0], {%1,%2,%3,%4};"
                 :: "l"(a), "f"(v.x), "f"(v.y), "f"(v.z), "f"(v.w)
                 : "memory");
}

// ---------------------------------------------------------------------------
// K5: fused epilogue + decode GEMM (f32x2, K-paired) + softmax.
// 8 nodes/block, 128 threads. cg = tid&63 -> cols cg*8..+7; rg = tid>>6 ->
// local nodes rg*4..rg*4+3.
__global__ __launch_bounds__(128) void k_dec(const float* __restrict__ b,
                                             float* __restrict__ out) {
    __shared__ __align__(16) float hs[8 * OC];  // 4 KB
    __shared__ float red[4][4];                 // [warp][local m]
    const int tid = threadIdx.x;
    const int warp = tid >> 5, lane = tid & 31;
    const int n0 = blockIdx.x * 8;
    const int cg = tid & 63, rg = tid >> 6;

    // h = relu(dis*(agg + y) + bias)
#pragma unroll
    for (int i = tid; i < 8 * OC; i += 128) {
        int m = i >> 7, c = i & 127;
        int n = n0 + m;
        size_t off = (size_t)n * OC + c;
        float v = g_dis[n] * (g_agg[off] + g_y[off]) + b[c];
        hs[i] = fmaxf(v, 0.f);
    }
    __syncthreads();

    const ulonglong2* hq = (const ulonglong2*)hs;  // 32 per node

    ull acc[4][8];
#pragma unroll
    for (int m = 0; m < 4; m++)
#pragma unroll
        for (int j = 0; j < 8; j++) acc[m][j] = 0ull;

    for (int kp = 0; kp < 64; kp += 4) {  // k step 8 over OC=128
        ulonglong2 hv[4][2];
#pragma unroll
        for (int m = 0; m < 4; m++) {
            int base = (rg * 4 + m) * 32 + (kp >> 1);
            hv[m][0] = hq[base];
            hv[m][1] = hq[base + 1];
        }
#pragma unroll
        for (int kp2 = 0; kp2 < 4; kp2++) {
            const ulonglong2* wbase = &g_WpD[(kp + kp2) * 256 + cg];  // [j*64 + cg]
            ulonglong2 w0 = wbase[0];
            ulonglong2 w1 = wbase[64];
            ulonglong2 w2 = wbase[128];
            ulonglong2 w3 = wbase[192];
#pragma unroll
            for (int m = 0; m < 4; m++) {
                ull xm = (kp2 & 1) ? hv[m][kp2 >> 1].y : hv[m][kp2 >> 1].x;
                fma2(acc[m][0], xm, w0.x);
                fma2(acc[m][1], xm, w0.y);
                fma2(acc[m][2], xm, w1.x);
                fma2(acc[m][3], xm, w1.y);
                fma2(acc[m][4], xm, w2.x);
                fma2(acc[m][5], xm, w2.y);
                fma2(acc[m][6], xm, w3.x);
                fma2(acc[m][7], xm, w3.y);
            }
        }
    }

    // logits for node (rg*4+m), cols cg*8+j
    float v[4][8];
#pragma unroll
    for (int m = 0; m < 4; m++) {
#pragma unroll
        for (int j = 0; j < 8; j++) {
            float2 p = up2(acc[m][j]);
            v[m][j] = p.x + p.y;
        }
    }

    // softmax over 512 cols = 64 cgs = 2 warps (warps rg*2, rg*2+1)
    // 1) max
#pragma unroll
    for (int m = 0; m < 4; m++) {
        float lm = v[m][0];
#pragma unroll
        for (int j = 1; j < 8; j++) lm = fmaxf(lm, v[m][j]);
#pragma unroll
        for (int o = 16; o; o >>= 1)
            lm = fmaxf(lm, __shfl_xor_sync(0xffffffffu, lm, o));
        if (lane == 0) red[warp][m] = lm;
    }
    __syncthreads();
    float rm[4];
#pragma unroll
    for (int m = 0; m < 4; m++)
        rm[m] = fmaxf(red[rg * 2][m], red[rg * 2 + 1][m]);
    __syncthreads();

    // 2) exp + sum
#pragma unroll
    for (int m = 0; m < 4; m++) {
        float ls = 0.f;
#pragma unroll
        for (int j = 0; j < 8; j++) {
            v[m][j] = __expf(v[m][j] - rm[m]);
            ls += v[m][j];
        }
#pragma unroll
        for (int o = 16; o; o >>= 1)
            ls += __shfl_xor_sync(0xffffffffu, ls, o);
        if (lane == 0) red[warp][m] = ls;
    }
    __syncthreads();

#pragma unroll
    for (int m = 0; m < 4; m++) {
        float inv = 1.f / (red[rg * 2][m] + red[rg * 2 + 1][m]);
        int row = n0 + rg * 4 + m;
        float4* o = (float4*)(out + (size_t)row * IC + cg * 8);
        o[0] = make_float4(v[m][0] * inv, v[m][1] * inv, v[m][2] * inv, v[m][3] * inv);
        o[1] = make_float4(v[m][4] * inv, v[m][5] * inv, v[m][6] * inv, v[m][7] * inv);
    }
}

// ---------------------------------------------------------------------------
extern "C" void kernel_launch(void* const* d_in, const int* in_sizes, int n_in,
                              void* d_out, int out_size) {
    const float* x    = (const float*)d_in[0];
    const int*   ei   = (const int*)d_in[1];
    const float* Wenc = (const float*)d_in[2];
    const float* benc = (const float*)d_in[3];
    const float* Wdec = (const float*)d_in[4];
    float*       out  = (float*)d_out;

    k_zero<<<2048, 256>>>();
    k_prep<<<64, 256>>>(Wenc, Wdec);
    k_deg<<<(NE + 255) / 256, 256>>>(ei);
    k_dis<<<(NN + 255) / 256, 256>>>();
    k_gemm1<<<(NN + 31) / 32, 128>>>(x);
    {
        long long threads = (long long)NE * 32;
        int blocks = (int)((threads + 255) / 256);
        k_edges<<<blocks, 256>>>(ei);
    }
    k_dec<<<NN / 8, 128>>>(benc, out);
}